// round 1
// baseline (speedup 1.0000x reference)
#include <cuda_runtime.h>

#define EPSF 1e-5f

// Precomputed categorical results: Y[g][cat][o] = sigmoid(GN(emb[g*100+cat]) @ W_cat[g] + b_cat[g])
// 100*100*128 floats = 5.12 MB (fits in L2)
__device__ __align__(16) float d_Y[100 * 100 * 128];

__device__ __forceinline__ float sigf(float x) { return 1.0f / (1.0f + __expf(-x)); }

// ---------------- Kernel 1: precompute Y ----------------
// grid (100 g, 4 row-tiles), 128 threads. Each block: W_cat[g] in smem,
// 25 embedding rows normalized + matmul'd.
__global__ __launch_bounds__(128) void precompute_Y(
    const float* __restrict__ emb_table,
    const float* __restrict__ gn_w, const float* __restrict__ gn_b,
    const float* __restrict__ W_cat, const float* __restrict__ b_cat)
{
    extern __shared__ float sh[];
    float* Wsh = sh;                 // 128*128
    float* Esh = sh + 128 * 128;     // 25 * 132 (pad 132: float4-aligned rows)
    __shared__ float s_mean[25], s_rstd[25];

    const int g    = blockIdx.x;     // 0..99
    const int tile = blockIdx.y;     // 0..3
    const int tid  = threadIdx.x;    // 0..127

    // Load W_cat[g] (64 KB) into shared, coalesced float4
    const float4* Wg4 = reinterpret_cast<const float4*>(W_cat + (size_t)g * 16384);
    float4* Wsh4 = reinterpret_cast<float4*>(Wsh);
    #pragma unroll
    for (int i = 0; i < 32; ++i) Wsh4[i * 128 + tid] = Wg4[i * 128 + tid];

    // Load 25 raw embedding rows
    const int row0 = tile * 25;
    #pragma unroll 5
    for (int r = 0; r < 25; ++r)
        Esh[r * 132 + tid] = emb_table[((size_t)(g * 100 + row0 + r)) * 128 + tid];
    __syncthreads();

    // Per-row mean / rstd (threads 0..24, one row each)
    if (tid < 25) {
        float s = 0.f, s2 = 0.f;
        #pragma unroll 8
        for (int k = 0; k < 128; ++k) {
            float v = Esh[tid * 132 + k];
            s += v; s2 += v * v;
        }
        float m   = s  * 0.0078125f;
        float var = fmaxf(s2 * 0.0078125f - m * m, 0.f);
        s_mean[tid] = m;
        s_rstd[tid] = rsqrtf(var + EPSF);
    }
    __syncthreads();

    // Normalize + affine, in place
    const float gw = gn_w[g * 128 + tid];
    const float gb = gn_b[g * 128 + tid];
    #pragma unroll 5
    for (int r = 0; r < 25; ++r)
        Esh[r * 132 + tid] = fmaf((Esh[r * 132 + tid] - s_mean[r]) * s_rstd[r], gw, gb);
    __syncthreads();

    // Matmul: thread = output column o; 25 row-accumulators
    float acc[25];
    const float bc = b_cat[g * 128 + tid];
    #pragma unroll
    for (int r = 0; r < 25; ++r) acc[r] = bc;

    for (int k4 = 0; k4 < 32; ++k4) {
        float w0 = Wsh[(k4 * 4 + 0) * 128 + tid];
        float w1 = Wsh[(k4 * 4 + 1) * 128 + tid];
        float w2 = Wsh[(k4 * 4 + 2) * 128 + tid];
        float w3 = Wsh[(k4 * 4 + 3) * 128 + tid];
        #pragma unroll
        for (int r = 0; r < 25; ++r) {
            float4 e = *reinterpret_cast<const float4*>(&Esh[r * 132 + k4 * 4]);
            acc[r] = fmaf(e.x, w0, acc[r]);
            acc[r] = fmaf(e.y, w1, acc[r]);
            acc[r] = fmaf(e.z, w2, acc[r]);
            acc[r] = fmaf(e.w, w3, acc[r]);
        }
    }
    #pragma unroll 5
    for (int r = 0; r < 25; ++r)
        d_Y[((size_t)(g * 100 + row0 + r)) * 128 + tid] = sigf(acc[r]);
}

// ---------------- Kernel 2: gather + num branch + transpose ----------------
// grid (2048 sample-pairs, 2 cond-halves), 256 threads.
// Staging sh[2][200][65]: pad 65 (odd) -> conflict-free column writes AND row reads.
__global__ __launch_bounds__(256) void fuse_main(
    const float* __restrict__ x_num, const int* __restrict__ x_cat,
    const float* __restrict__ W_num, const float* __restrict__ b_num,
    float* __restrict__ out)
{
    extern __shared__ float sh[];    // 2*200*65 = 26000 floats
    __shared__ int   s_cat[200];
    __shared__ float s_num[200];

    const int tid = threadIdx.x;
    const int b0  = blockIdx.x * 2;
    const int ob  = blockIdx.y * 64;   // cond-base for this half

    if (tid < 200) {
        int s = (tid >= 100) ? 1 : 0;
        int i = tid - s * 100;
        s_cat[tid] = x_cat[(b0 + s) * 100 + i];
        s_num[tid] = x_num[(b0 + s) * 100 + i];
    }
    __syncthreads();

    // Phase A: gather categorical rows from Y (200 rows x 16 float4)
    for (int idx = tid; idx < 3200; idx += 256) {
        int rr = idx >> 4;            // 0..199 : (s,g)
        int o4 = idx & 15;
        int s  = (rr >= 100) ? 1 : 0;
        int g  = rr - s * 100;
        int cat = s_cat[rr];
        float4 v = *reinterpret_cast<const float4*>(
            &d_Y[((size_t)(g * 100 + cat)) * 128 + ob + o4 * 4]);
        float* dst = &sh[(s * 200 + 100 + g) * 65 + o4 * 4];
        dst[0] = v.x; dst[1] = v.y; dst[2] = v.z; dst[3] = v.w;
    }

    // Phase B: numerical branch (200 rows x 16 float4 of W/b)
    for (int idx = tid; idx < 3200; idx += 256) {
        int rr = idx >> 4;
        int o4 = idx & 15;
        int s  = (rr >= 100) ? 1 : 0;
        int i  = rr - s * 100;
        float xv = s_num[rr];
        float4 w  = *reinterpret_cast<const float4*>(&W_num[i * 128 + ob + o4 * 4]);
        float4 bb = *reinterpret_cast<const float4*>(&b_num[i * 128 + ob + o4 * 4]);
        float* dst = &sh[(s * 200 + i) * 65 + o4 * 4];
        dst[0] = sigf(fmaf(xv, w.x, bb.x));
        dst[1] = sigf(fmaf(xv, w.y, bb.y));
        dst[2] = sigf(fmaf(xv, w.z, bb.z));
        dst[3] = sigf(fmaf(xv, w.w, bb.w));
    }
    __syncthreads();

    // Phase C: transposed, fully coalesced output write
    // out[(b0+s)*25600 + (ob+o)*200 + t] = sh[(s*200 + t)*65 + o]
    for (int idx = tid; idx < 25600; idx += 256) {
        int s   = (idx >= 12800) ? 1 : 0;
        int rem = idx - s * 12800;
        int o   = rem / 200;
        int t   = rem - o * 200;
        out[(size_t)(b0 + s) * 25600 + (size_t)(ob + o) * 200 + t]
            = sh[(s * 200 + t) * 65 + o];
    }
}

extern "C" void kernel_launch(void* const* d_in, const int* in_sizes, int n_in,
                              void* d_out, int out_size) {
    const float* x_num = (const float*)d_in[0];
    const int*   x_cat = (const int*)  d_in[1];
    const float* W_num = (const float*)d_in[2];
    const float* b_num = (const float*)d_in[3];
    const float* emb   = (const float*)d_in[4];
    const float* gn_w  = (const float*)d_in[5];
    const float* gn_b  = (const float*)d_in[6];
    const float* W_cat = (const float*)d_in[7];
    const float* b_cat = (const float*)d_in[8];
    float* out = (float*)d_out;

    const int smem_pre  = (128 * 128 + 25 * 132) * 4;   // 78736 B
    const int smem_main = 2 * 200 * 65 * 4;             // 104000 B
    cudaFuncSetAttribute(precompute_Y, cudaFuncAttributeMaxDynamicSharedMemorySize, smem_pre);
    cudaFuncSetAttribute(fuse_main,    cudaFuncAttributeMaxDynamicSharedMemorySize, smem_main);

    precompute_Y<<<dim3(100, 4), 128, smem_pre>>>(emb, gn_w, gn_b, W_cat, b_cat);
    fuse_main<<<dim3(2048, 2), 256, smem_main>>>(x_num, x_cat, W_num, b_num, out);
}

// round 5
// speedup vs baseline: 1.4298x; 1.4298x over previous
#include <cuda_runtime.h>

#define EPSF 1e-5f

// Precomputed categorical results: Y[g][cat][o] = sigmoid(GN(emb[g*100+cat]) @ W_cat[g] + b_cat[g])
__device__ __align__(16) float d_Y[100 * 100 * 128];
// Transposed num weights: WnumT[o][i] = W_num[i][o]  (128 x 100)
__device__ __align__(16) float d_WnumT[128 * 100];
__device__ __align__(16) float d_bnumT[128 * 100];

__device__ __forceinline__ float sigf(float x) { return 1.0f / (1.0f + __expf(-x)); }

__device__ __forceinline__ float sig_tanh(float x) {
    // sigmoid(x) = 0.5*tanh(0.5x) + 0.5 ; MUFU.TANH (1 SFU op)
    float t;
    asm("tanh.approx.f32 %0, %1;" : "=f"(t) : "f"(0.5f * x));
    return fmaf(0.5f, t, 0.5f);
}

// ---------------- Kernel 0: transpose W_num/b_num ----------------
__global__ __launch_bounds__(256) void transpose_wb(
    const float* __restrict__ W_num, const float* __restrict__ b_num)
{
    int idx = blockIdx.x * 256 + threadIdx.x;   // over 128*100
    if (idx < 12800) {
        int o = idx / 100;
        int i = idx - o * 100;
        d_WnumT[idx] = W_num[i * 128 + o];
        d_bnumT[idx] = b_num[i * 128 + o];
    }
}

// ---------------- Kernel 1: precompute Y ----------------
__global__ __launch_bounds__(128) void precompute_Y(
    const float* __restrict__ emb_table,
    const float* __restrict__ gn_w, const float* __restrict__ gn_b,
    const float* __restrict__ W_cat, const float* __restrict__ b_cat)
{
    extern __shared__ float sh[];
    float* Wsh = sh;                 // 128*128
    float* Esh = sh + 128 * 128;     // 25 * 132
    __shared__ float s_mean[25], s_rstd[25];

    const int g    = blockIdx.x;
    const int tile = blockIdx.y;
    const int tid  = threadIdx.x;

    const float4* Wg4 = reinterpret_cast<const float4*>(W_cat + (size_t)g * 16384);
    float4* Wsh4 = reinterpret_cast<float4*>(Wsh);
    #pragma unroll
    for (int i = 0; i < 32; ++i) Wsh4[i * 128 + tid] = Wg4[i * 128 + tid];

    const int row0 = tile * 25;
    #pragma unroll 5
    for (int r = 0; r < 25; ++r)
        Esh[r * 132 + tid] = emb_table[((size_t)(g * 100 + row0 + r)) * 128 + tid];
    __syncthreads();

    if (tid < 25) {
        float s = 0.f, s2 = 0.f;
        #pragma unroll 8
        for (int k = 0; k < 128; ++k) {
            float v = Esh[tid * 132 + k];
            s += v; s2 += v * v;
        }
        float m   = s  * 0.0078125f;
        float var = fmaxf(s2 * 0.0078125f - m * m, 0.f);
        s_mean[tid] = m;
        s_rstd[tid] = rsqrtf(var + EPSF);
    }
    __syncthreads();

    const float gw = gn_w[g * 128 + tid];
    const float gb = gn_b[g * 128 + tid];
    #pragma unroll 5
    for (int r = 0; r < 25; ++r)
        Esh[r * 132 + tid] = fmaf((Esh[r * 132 + tid] - s_mean[r]) * s_rstd[r], gw, gb);
    __syncthreads();

    float acc[25];
    const float bc = b_cat[g * 128 + tid];
    #pragma unroll
    for (int r = 0; r < 25; ++r) acc[r] = bc;

    for (int k4 = 0; k4 < 32; ++k4) {
        float w0 = Wsh[(k4 * 4 + 0) * 128 + tid];
        float w1 = Wsh[(k4 * 4 + 1) * 128 + tid];
        float w2 = Wsh[(k4 * 4 + 2) * 128 + tid];
        float w3 = Wsh[(k4 * 4 + 3) * 128 + tid];
        #pragma unroll
        for (int r = 0; r < 25; ++r) {
            float4 e = *reinterpret_cast<const float4*>(&Esh[r * 132 + k4 * 4]);
            acc[r] = fmaf(e.x, w0, acc[r]);
            acc[r] = fmaf(e.y, w1, acc[r]);
            acc[r] = fmaf(e.z, w2, acc[r]);
            acc[r] = fmaf(e.w, w3, acc[r]);
        }
    }
    #pragma unroll 5
    for (int r = 0; r < 25; ++r)
        d_Y[((size_t)(g * 100 + row0 + r)) * 128 + tid] = sigf(acc[r]);
}

// ---------------- Kernel 2: fused gather + num branch ----------------
// grid (4096 samples, 2 cond-halves), 256 threads, 8 blocks/SM.
// Cat part staged transposed in smem sh[o_local][g]; num part written directly
// via pre-transposed WnumT/bnumT (no staging needed).
__global__ __launch_bounds__(256, 8) void fuse_main(
    const float* __restrict__ x_num, const int* __restrict__ x_cat,
    float* __restrict__ out)
{
    __shared__ float sh[64 * 100];   // cat staging, 25.6 KB
    __shared__ int   s_cat[100];
    __shared__ float s_num[100];

    const int tid = threadIdx.x;
    const int b   = blockIdx.x;
    const int ob  = blockIdx.y * 64;             // cond-base for this half
    float* outb = out + (size_t)b * 25600;

    if (tid < 100)      s_cat[tid]       = x_cat[b * 100 + tid];
    else if (tid < 200) s_num[tid - 100] = x_num[b * 100 + (tid - 100)];
    __syncthreads();

    // Phase A: gather cat rows from Y into transposed staging.
    // idx = o4*100 + g (g fastest within warp -> conflict-free strided STS)
    #pragma unroll 2
    for (int idx = tid; idx < 1600; idx += 256) {
        int o4 = idx / 100;
        int g  = idx - o4 * 100;
        float4 v = *reinterpret_cast<const float4*>(
            &d_Y[(g * 100 + s_cat[g]) * 128 + ob + o4 * 4]);
        sh[(o4 * 4 + 0) * 100 + g] = v.x;
        sh[(o4 * 4 + 1) * 100 + g] = v.y;
        sh[(o4 * 4 + 2) * 100 + g] = v.z;
        sh[(o4 * 4 + 3) * 100 + g] = v.w;
    }

    // Phase B: numerical branch, direct coalesced write (no staging).
    // idx = o*25 + i4 (i4 fastest -> coalesced WnumT loads and out stores)
    #pragma unroll 2
    for (int idx = tid; idx < 1600; idx += 256) {
        int o  = idx / 25;
        int i4 = idx - o * 25;
        float4 w  = *reinterpret_cast<const float4*>(&d_WnumT[(ob + o) * 100 + i4 * 4]);
        float4 bb = *reinterpret_cast<const float4*>(&d_bnumT[(ob + o) * 100 + i4 * 4]);
        float4 r;
        r.x = sig_tanh(fmaf(s_num[i4 * 4 + 0], w.x, bb.x));
        r.y = sig_tanh(fmaf(s_num[i4 * 4 + 1], w.y, bb.y));
        r.z = sig_tanh(fmaf(s_num[i4 * 4 + 2], w.z, bb.z));
        r.w = sig_tanh(fmaf(s_num[i4 * 4 + 3], w.w, bb.w));
        *reinterpret_cast<float4*>(&outb[(size_t)(ob + o) * 200 + i4 * 4]) = r;
    }
    __syncthreads();

    // Phase C: cat output, vectorized LDS.128 + STG.128.
    #pragma unroll 2
    for (int idx = tid; idx < 1600; idx += 256) {
        int o  = idx / 25;
        int g4 = idx - o * 25;
        float4 v = *reinterpret_cast<const float4*>(&sh[o * 100 + g4 * 4]);
        *reinterpret_cast<float4*>(&outb[(size_t)(ob + o) * 200 + 100 + g4 * 4]) = v;
    }
}

extern "C" void kernel_launch(void* const* d_in, const int* in_sizes, int n_in,
                              void* d_out, int out_size) {
    const float* x_num = (const float*)d_in[0];
    const int*   x_cat = (const int*)  d_in[1];
    const float* W_num = (const float*)d_in[2];
    const float* b_num = (const float*)d_in[3];
    const float* emb   = (const float*)d_in[4];
    const float* gn_w  = (const float*)d_in[5];
    const float* gn_b  = (const float*)d_in[6];
    const float* W_cat = (const float*)d_in[7];
    const float* b_cat = (const float*)d_in[8];
    float* out = (float*)d_out;

    const int smem_pre = (128 * 128 + 25 * 132) * 4;
    cudaFuncSetAttribute(precompute_Y, cudaFuncAttributeMaxDynamicSharedMemorySize, smem_pre);

    transpose_wb<<<50, 256>>>(W_num, b_num);
    precompute_Y<<<dim3(100, 4), 128, smem_pre>>>(emb, gn_w, gn_b, W_cat, b_cat);
    fuse_main<<<dim3(4096, 2), 256>>>(x_num, x_cat, out);
}